// round 2
// baseline (speedup 1.0000x reference)
#include <cuda_runtime.h>
#include <cuda_bf16.h>

#define N_GROUPS 256
#define EMBED 1024
#define VEC (EMBED / 4)   // 256 float4 per row

// Scratch (device globals; no allocation allowed)
__device__ float g_im_mean[N_GROUPS * EMBED];
__device__ float g_s_mean[N_GROUPS * EMBED];
__device__ float g_S[N_GROUPS * N_GROUPS];

// ---------------------------------------------------------------------------
// Kernel 1: segment mean of embeddings.
// Blocks 0..255: groups of `im` (counts = num_clips)
// Blocks 256..511: groups of `s` (counts = num_caps)
// Each block: scan counts (shared), then 256 threads each own one float4 column
// chunk and accumulate over the group's rows.
// ---------------------------------------------------------------------------
__global__ void __launch_bounds__(256) segmean_kernel(
    const float* __restrict__ im, const float* __restrict__ s,
    const int* __restrict__ num_clips, const int* __restrict__ num_caps)
{
    __shared__ int offs[N_GROUPS];
    const int b = blockIdx.x;
    const bool is_im = (b < N_GROUPS);
    const int g = is_im ? b : b - N_GROUPS;
    const int* __restrict__ cnt = is_im ? num_clips : num_caps;
    const float4* __restrict__ src = (const float4*)(is_im ? im : s);
    float4* __restrict__ dst = (float4*)(is_im ? g_im_mean : g_s_mean);

    const int t = threadIdx.x;

    // inclusive scan of counts (Hillis-Steele in shared)
    offs[t] = cnt[t];
    __syncthreads();
    #pragma unroll
    for (int d = 1; d < N_GROUPS; d <<= 1) {
        int add = (t >= d) ? offs[t - d] : 0;
        __syncthreads();
        offs[t] += add;
        __syncthreads();
    }
    const int end = offs[g];
    const int start = (g == 0) ? 0 : offs[g - 1];
    const int n = end - start;
    const float inv = 1.0f / (float)n;

    const float4* p = src + (size_t)start * VEC + t;
    float ax = 0.f, ay = 0.f, az = 0.f, aw = 0.f;
    for (int r = 0; r < n; r++) {
        float4 x = p[(size_t)r * VEC];
        ax += x.x; ay += x.y; az += x.z; aw += x.w;
    }
    float4 o;
    o.x = ax * inv; o.y = ay * inv; o.z = az * inv; o.w = aw * inv;
    dst[(size_t)g * VEC + t] = o;
}

// ---------------------------------------------------------------------------
// Kernel 2: S[256][256] = IMmean @ SMean^T   (block means already scaled)
// Grid (8,8), 256 threads, 32x32 output tile, K-chunks of 32 via shared mem.
// Each thread computes a 2x2 micro-tile.
// ---------------------------------------------------------------------------
__global__ void __launch_bounds__(256) gemm_kernel()
{
    __shared__ float As[32][33];
    __shared__ float Bs[32][33];

    const int tid = threadIdx.x;
    const int tx = tid & 15;
    const int ty = tid >> 4;
    const int bi = blockIdx.y * 32;   // rows of S (im groups)
    const int bj = blockIdx.x * 32;   // cols of S (s groups)

    const int lr = tid >> 3;          // load row    0..31
    const int lc = (tid & 7) * 4;     // load col    0,4,..,28

    float a00 = 0.f, a01 = 0.f, a10 = 0.f, a11 = 0.f;

    for (int k0 = 0; k0 < EMBED; k0 += 32) {
        float4 a = *(const float4*)&g_im_mean[(size_t)(bi + lr) * EMBED + k0 + lc];
        float4 bv = *(const float4*)&g_s_mean[(size_t)(bj + lr) * EMBED + k0 + lc];
        As[lr][lc + 0] = a.x;  As[lr][lc + 1] = a.y;
        As[lr][lc + 2] = a.z;  As[lr][lc + 3] = a.w;
        Bs[lr][lc + 0] = bv.x; Bs[lr][lc + 1] = bv.y;
        Bs[lr][lc + 2] = bv.z; Bs[lr][lc + 3] = bv.w;
        __syncthreads();
        #pragma unroll
        for (int kk = 0; kk < 32; kk++) {
            float x0 = As[ty][kk];
            float x1 = As[ty + 16][kk];
            float y0 = Bs[tx][kk];
            float y1 = Bs[tx + 16][kk];
            a00 += x0 * y0;
            a01 += x0 * y1;
            a10 += x1 * y0;
            a11 += x1 * y1;
        }
        __syncthreads();
    }

    g_S[(bi + ty)      * N_GROUPS + bj + tx]      = a00;
    g_S[(bi + ty)      * N_GROUPS + bj + tx + 16] = a01;
    g_S[(bi + ty + 16) * N_GROUPS + bj + tx]      = a10;
    g_S[(bi + ty + 16) * N_GROUPS + bj + tx + 16] = a11;
}

// ---------------------------------------------------------------------------
// Kernel 3: hinge loss reduction. One block, 1024 threads, deterministic.
// loss = sum_{i != j} [ max(S_ij - S_ii, 0) + max(S_ij - S_jj, 0) ]
// ---------------------------------------------------------------------------
__global__ void __launch_bounds__(1024) loss_kernel(float* __restrict__ out)
{
    __shared__ float diag[N_GROUPS];
    __shared__ float red[32];
    const int t = threadIdx.x;

    if (t < N_GROUPS) diag[t] = g_S[t * (N_GROUPS + 1)];
    __syncthreads();

    float sum = 0.f;
    for (int idx = t; idx < N_GROUPS * N_GROUPS; idx += 1024) {
        int i = idx >> 8;
        int j = idx & 255;
        if (i != j) {
            float v = g_S[idx];
            sum += fmaxf(v - diag[i], 0.f) + fmaxf(v - diag[j], 0.f);
        }
    }
    #pragma unroll
    for (int o = 16; o; o >>= 1) sum += __shfl_xor_sync(0xFFFFFFFFu, sum, o);
    if ((t & 31) == 0) red[t >> 5] = sum;
    __syncthreads();
    if (t < 32) {
        float v = red[t];
        #pragma unroll
        for (int o = 16; o; o >>= 1) v += __shfl_xor_sync(0xFFFFFFFFu, v, o);
        if (t == 0) out[0] = v;
    }
}

extern "C" void kernel_launch(void* const* d_in, const int* in_sizes, int n_in,
                              void* d_out, int out_size)
{
    const float* im        = (const float*)d_in[0];
    const float* s         = (const float*)d_in[1];
    const int*   num_clips = (const int*)d_in[2];
    const int*   num_caps  = (const int*)d_in[3];
    float* out = (float*)d_out;

    segmean_kernel<<<512, 256>>>(im, s, num_clips, num_caps);
    gemm_kernel<<<dim3(8, 8), 256>>>();
    loss_kernel<<<1, 1024>>>(out);
}

// round 3
// speedup vs baseline: 1.7945x; 1.7945x over previous
#include <cuda_runtime.h>
#include <cuda_bf16.h>

#define N_GROUPS 256
#define EMBED 1024
#define VEC (EMBED / 4)   // 256 float4 per row
#define KSPLIT 8

// Scratch (device globals; no allocation allowed)
__device__ float g_im_mean[N_GROUPS * EMBED];
__device__ float g_s_mean[N_GROUPS * EMBED];
__device__ float g_Spart[KSPLIT * N_GROUPS * N_GROUPS];
__device__ float g_S[N_GROUPS * N_GROUPS];
__device__ float g_diag[N_GROUPS];

// ---------------------------------------------------------------------------
// Kernel 1: segment mean. Grid = 1024 blocks of 128 threads.
//   blockIdx.x encodes (group g, source, column-half).
// Each block computes its group's start offset with a block reduction over the
// count array, then each thread accumulates one float4 column over the rows.
// ---------------------------------------------------------------------------
__global__ void __launch_bounds__(128) segmean_kernel(
    const float* __restrict__ im, const float* __restrict__ s,
    const int* __restrict__ num_clips, const int* __restrict__ num_caps)
{
    const int b = blockIdx.x;
    const int g = b >> 2;
    const bool is_im = ((b >> 1) & 1) == 0;
    const int half = b & 1;
    const int* __restrict__ cnt = is_im ? num_clips : num_caps;
    const float4* __restrict__ src = (const float4*)(is_im ? im : s);
    float4* __restrict__ dst = (float4*)(is_im ? g_im_mean : g_s_mean);

    const int t = threadIdx.x;

    // start = sum of counts with index < g (block reduction, 2 counts/thread)
    int c0 = cnt[t];
    int c1 = cnt[t + 128];
    int contrib = ((t < g) ? c0 : 0) + ((t + 128 < g) ? c1 : 0);
    #pragma unroll
    for (int o = 16; o; o >>= 1) contrib += __shfl_xor_sync(0xFFFFFFFFu, contrib, o);
    __shared__ int ws[4];
    if ((t & 31) == 0) ws[t >> 5] = contrib;
    __syncthreads();
    const int start = ws[0] + ws[1] + ws[2] + ws[3];
    const int n = cnt[g];
    const float inv = 1.0f / (float)n;

    const float4* p = src + (size_t)start * VEC + half * 128 + t;

    float ax0 = 0.f, ay0 = 0.f, az0 = 0.f, aw0 = 0.f;
    float ax1 = 0.f, ay1 = 0.f, az1 = 0.f, aw1 = 0.f;
    int r = 0;
    for (; r + 2 <= n; r += 2) {
        float4 x0 = p[(size_t)r * VEC];
        float4 x1 = p[(size_t)(r + 1) * VEC];
        ax0 += x0.x; ay0 += x0.y; az0 += x0.z; aw0 += x0.w;
        ax1 += x1.x; ay1 += x1.y; az1 += x1.z; aw1 += x1.w;
    }
    if (r < n) {
        float4 x0 = p[(size_t)r * VEC];
        ax0 += x0.x; ay0 += x0.y; az0 += x0.z; aw0 += x0.w;
    }
    float4 o4;
    o4.x = (ax0 + ax1) * inv;
    o4.y = (ay0 + ay1) * inv;
    o4.z = (az0 + az1) * inv;
    o4.w = (aw0 + aw1) * inv;
    dst[(size_t)g * VEC + half * 128 + t] = o4;
}

// ---------------------------------------------------------------------------
// Kernel 2: K-split GEMM partials. Grid (4,4,KSPLIT), 256 threads.
// 64x64 output tile, K=128 per split in chunks of 16, 4x4 microtile/thread.
// Smem stored k-major (As[k][m], stride 68 floats => 16B aligned, conflict-free
// STS fill and LDS.128 inner loads).
// ---------------------------------------------------------------------------
__global__ void __launch_bounds__(256) gemm_partial_kernel()
{
    __shared__ float As[16][68];
    __shared__ float Bs[16][68];

    const int tid = threadIdx.x;
    const int tx = tid & 15;
    const int ty = tid >> 4;
    const int bi = blockIdx.y * 64;
    const int bj = blockIdx.x * 64;
    const int kbase = blockIdx.z * (EMBED / KSPLIT);

    const int lr = tid >> 2;   // 0..63 : tile row to load
    const int lc = tid & 3;    // 0..3  : k-quad to load

    float acc[4][4] = {};

    for (int k0 = 0; k0 < EMBED / KSPLIT; k0 += 16) {
        float4 a  = *(const float4*)&g_im_mean[(size_t)(bi + lr) * EMBED + kbase + k0 + lc * 4];
        float4 bv = *(const float4*)&g_s_mean [(size_t)(bj + lr) * EMBED + kbase + k0 + lc * 4];
        As[lc * 4 + 0][lr] = a.x;  As[lc * 4 + 1][lr] = a.y;
        As[lc * 4 + 2][lr] = a.z;  As[lc * 4 + 3][lr] = a.w;
        Bs[lc * 4 + 0][lr] = bv.x; Bs[lc * 4 + 1][lr] = bv.y;
        Bs[lc * 4 + 2][lr] = bv.z; Bs[lc * 4 + 3][lr] = bv.w;
        __syncthreads();
        #pragma unroll
        for (int kk = 0; kk < 16; kk++) {
            float4 av = *(const float4*)&As[kk][ty * 4];
            float4 bw = *(const float4*)&Bs[kk][tx * 4];
            acc[0][0] += av.x * bw.x; acc[0][1] += av.x * bw.y;
            acc[0][2] += av.x * bw.z; acc[0][3] += av.x * bw.w;
            acc[1][0] += av.y * bw.x; acc[1][1] += av.y * bw.y;
            acc[1][2] += av.y * bw.z; acc[1][3] += av.y * bw.w;
            acc[2][0] += av.z * bw.x; acc[2][1] += av.z * bw.y;
            acc[2][2] += av.z * bw.z; acc[2][3] += av.z * bw.w;
            acc[3][0] += av.w * bw.x; acc[3][1] += av.w * bw.y;
            acc[3][2] += av.w * bw.z; acc[3][3] += av.w * bw.w;
        }
        __syncthreads();
    }

    float* outp = g_Spart + (size_t)blockIdx.z * N_GROUPS * N_GROUPS;
    #pragma unroll
    for (int i = 0; i < 4; i++) {
        float4 v;
        v.x = acc[i][0]; v.y = acc[i][1]; v.z = acc[i][2]; v.w = acc[i][3];
        *(float4*)&outp[(size_t)(bi + ty * 4 + i) * N_GROUPS + bj + tx * 4] = v;
    }
}

// ---------------------------------------------------------------------------
// Kernel 3: reduce K-split partials -> g_S, extract diagonal -> g_diag.
// Grid 64 blocks x 256 threads, one float4 per thread (16384 float4 total).
// ---------------------------------------------------------------------------
__global__ void __launch_bounds__(256) reduce_kernel()
{
    const int q = blockIdx.x * 256 + threadIdx.x;   // 0..16383
    float4 v = make_float4(0.f, 0.f, 0.f, 0.f);
    #pragma unroll
    for (int z = 0; z < KSPLIT; z++) {
        float4 p = *(const float4*)&g_Spart[(size_t)z * N_GROUPS * N_GROUPS + q * 4];
        v.x += p.x; v.y += p.y; v.z += p.z; v.w += p.w;
    }
    *(float4*)&g_S[q * 4] = v;

    const int i = q >> 6;              // row
    const int j0 = (q & 63) * 4;       // first col of this float4
    if (i >= j0 && i < j0 + 4) {
        float d = (i == j0) ? v.x : (i == j0 + 1) ? v.y : (i == j0 + 2) ? v.z : v.w;
        g_diag[i] = d;
    }
}

// ---------------------------------------------------------------------------
// Kernel 4: hinge loss. One block, 1024 threads, float4 reads, smem diag.
// loss = sum_{i != j} [ max(S_ij - S_ii, 0) + max(S_ij - S_jj, 0) ]
// ---------------------------------------------------------------------------
__global__ void __launch_bounds__(1024) loss_kernel(float* __restrict__ out)
{
    __shared__ float diag_s[N_GROUPS];
    __shared__ float red[32];
    const int t = threadIdx.x;

    if (t < N_GROUPS) diag_s[t] = g_diag[t];
    __syncthreads();

    float sum = 0.f;
    #pragma unroll
    for (int q = t; q < 16384; q += 1024) {
        float4 v = *(const float4*)&g_S[q * 4];
        const int i = q >> 6;
        const int j0 = (q & 63) * 4;
        const float di = diag_s[i];
        float vv[4] = {v.x, v.y, v.z, v.w};
        #pragma unroll
        for (int c = 0; c < 4; c++) {
            int j = j0 + c;
            if (j != i)
                sum += fmaxf(vv[c] - di, 0.f) + fmaxf(vv[c] - diag_s[j], 0.f);
        }
    }
    #pragma unroll
    for (int o = 16; o; o >>= 1) sum += __shfl_xor_sync(0xFFFFFFFFu, sum, o);
    if ((t & 31) == 0) red[t >> 5] = sum;
    __syncthreads();
    if (t < 32) {
        float v = red[t];
        #pragma unroll
        for (int o = 16; o; o >>= 1) v += __shfl_xor_sync(0xFFFFFFFFu, v, o);
        if (t == 0) out[0] = v;
    }
}

extern "C" void kernel_launch(void* const* d_in, const int* in_sizes, int n_in,
                              void* d_out, int out_size)
{
    const float* im        = (const float*)d_in[0];
    const float* s         = (const float*)d_in[1];
    const int*   num_clips = (const int*)d_in[2];
    const int*   num_caps  = (const int*)d_in[3];
    float* out = (float*)d_out;

    segmean_kernel<<<1024, 128>>>(im, s, num_clips, num_caps);
    gemm_partial_kernel<<<dim3(4, 4, KSPLIT), 256>>>();
    reduce_kernel<<<64, 256>>>();
    loss_kernel<<<1, 1024>>>(out);
}

// round 5
// speedup vs baseline: 2.1994x; 1.2257x over previous
#include <cuda_runtime.h>
#include <cuda_bf16.h>

#define N_GROUPS 256
#define EMBED 1024
#define VEC (EMBED / 4)   // 256 float4 per row
#define KSPLIT 8
#define NPART (N_GROUPS * N_GROUPS)   // 65536

// Scratch (device globals; no allocation allowed)
__device__ float g_im_mean[N_GROUPS * EMBED];
__device__ float g_s_mean[N_GROUPS * EMBED];
__device__ float g_Spart[KSPLIT * NPART];
__device__ float g_loss_part[64];
__device__ int   g_count;   // zero-init at load; reset by last block each launch

// ---------------------------------------------------------------------------
// Kernel 1: segment mean. Grid = 1024 blocks of 128 threads.
//   blockIdx.x encodes (group g, source, column-half).
// ---------------------------------------------------------------------------
__global__ void __launch_bounds__(128) segmean_kernel(
    const float* __restrict__ im, const float* __restrict__ s,
    const int* __restrict__ num_clips, const int* __restrict__ num_caps)
{
    const int b = blockIdx.x;
    const int g = b >> 2;
    const bool is_im = ((b >> 1) & 1) == 0;
    const int half = b & 1;
    const int* __restrict__ cnt = is_im ? num_clips : num_caps;
    const float4* __restrict__ src = (const float4*)(is_im ? im : s);
    float4* __restrict__ dst = (float4*)(is_im ? g_im_mean : g_s_mean);

    const int t = threadIdx.x;

    // start = sum of counts with index < g (block reduction, 2 counts/thread)
    int c0 = cnt[t];
    int c1 = cnt[t + 128];
    int contrib = ((t < g) ? c0 : 0) + ((t + 128 < g) ? c1 : 0);
    #pragma unroll
    for (int o = 16; o; o >>= 1) contrib += __shfl_xor_sync(0xFFFFFFFFu, contrib, o);
    __shared__ int ws[4];
    if ((t & 31) == 0) ws[t >> 5] = contrib;
    __syncthreads();
    const int start = ws[0] + ws[1] + ws[2] + ws[3];
    const int n = cnt[g];
    const float inv = 1.0f / (float)n;

    const float4* p = src + (size_t)start * VEC + half * 128 + t;

    float ax0 = 0.f, ay0 = 0.f, az0 = 0.f, aw0 = 0.f;
    float ax1 = 0.f, ay1 = 0.f, az1 = 0.f, aw1 = 0.f;
    float ax2 = 0.f, ay2 = 0.f, az2 = 0.f, aw2 = 0.f;
    float ax3 = 0.f, ay3 = 0.f, az3 = 0.f, aw3 = 0.f;
    int r = 0;
    for (; r + 4 <= n; r += 4) {
        float4 x0 = p[(size_t)(r + 0) * VEC];
        float4 x1 = p[(size_t)(r + 1) * VEC];
        float4 x2 = p[(size_t)(r + 2) * VEC];
        float4 x3 = p[(size_t)(r + 3) * VEC];
        ax0 += x0.x; ay0 += x0.y; az0 += x0.z; aw0 += x0.w;
        ax1 += x1.x; ay1 += x1.y; az1 += x1.z; aw1 += x1.w;
        ax2 += x2.x; ay2 += x2.y; az2 += x2.z; aw2 += x2.w;
        ax3 += x3.x; ay3 += x3.y; az3 += x3.z; aw3 += x3.w;
    }
    for (; r < n; r++) {
        float4 x0 = p[(size_t)r * VEC];
        ax0 += x0.x; ay0 += x0.y; az0 += x0.z; aw0 += x0.w;
    }
    float4 o4;
    o4.x = (ax0 + ax1 + ax2 + ax3) * inv;
    o4.y = (ay0 + ay1 + ay2 + ay3) * inv;
    o4.z = (az0 + az1 + az2 + az3) * inv;
    o4.w = (aw0 + aw1 + aw2 + aw3) * inv;
    dst[(size_t)g * VEC + half * 128 + t] = o4;
}

// ---------------------------------------------------------------------------
// Kernel 2: K-split GEMM partials. Grid (4,4,KSPLIT), 256 threads.
// 64x64 output tile, K=128 per split in chunks of 16, 4x4 microtile/thread.
// ---------------------------------------------------------------------------
__global__ void __launch_bounds__(256) gemm_partial_kernel()
{
    __shared__ float As[16][68];
    __shared__ float Bs[16][68];

    const int tid = threadIdx.x;
    const int tx = tid & 15;
    const int ty = tid >> 4;
    const int bi = blockIdx.y * 64;
    const int bj = blockIdx.x * 64;
    const int kbase = blockIdx.z * (EMBED / KSPLIT);

    const int lr = tid >> 2;   // 0..63 : tile row to load
    const int lc = tid & 3;    // 0..3  : k-quad to load

    float acc[4][4] = {};

    for (int k0 = 0; k0 < EMBED / KSPLIT; k0 += 16) {
        float4 a  = *(const float4*)&g_im_mean[(size_t)(bi + lr) * EMBED + kbase + k0 + lc * 4];
        float4 bv = *(const float4*)&g_s_mean [(size_t)(bj + lr) * EMBED + kbase + k0 + lc * 4];
        As[lc * 4 + 0][lr] = a.x;  As[lc * 4 + 1][lr] = a.y;
        As[lc * 4 + 2][lr] = a.z;  As[lc * 4 + 3][lr] = a.w;
        Bs[lc * 4 + 0][lr] = bv.x; Bs[lc * 4 + 1][lr] = bv.y;
        Bs[lc * 4 + 2][lr] = bv.z; Bs[lc * 4 + 3][lr] = bv.w;
        __syncthreads();
        #pragma unroll
        for (int kk = 0; kk < 16; kk++) {
            float4 av = *(const float4*)&As[kk][ty * 4];
            float4 bw = *(const float4*)&Bs[kk][tx * 4];
            acc[0][0] += av.x * bw.x; acc[0][1] += av.x * bw.y;
            acc[0][2] += av.x * bw.z; acc[0][3] += av.x * bw.w;
            acc[1][0] += av.y * bw.x; acc[1][1] += av.y * bw.y;
            acc[1][2] += av.y * bw.z; acc[1][3] += av.y * bw.w;
            acc[2][0] += av.z * bw.x; acc[2][1] += av.z * bw.y;
            acc[2][2] += av.z * bw.z; acc[2][3] += av.z * bw.w;
            acc[3][0] += av.w * bw.x; acc[3][1] += av.w * bw.y;
            acc[3][2] += av.w * bw.z; acc[3][3] += av.w * bw.w;
        }
        __syncthreads();
    }

    float* outp = g_Spart + (size_t)blockIdx.z * NPART;
    #pragma unroll
    for (int i = 0; i < 4; i++) {
        float4 v;
        v.x = acc[i][0]; v.y = acc[i][1]; v.z = acc[i][2]; v.w = acc[i][3];
        *(float4*)&outp[(size_t)(bi + ty * 4 + i) * N_GROUPS + bj + tx * 4] = v;
    }
}

// ---------------------------------------------------------------------------
// Kernel 3: fused K-split reduce + diag + hinge loss.
// Grid 64 blocks x 256 threads. Each block:
//   - rebuilds all 256 diag values (each thread sums 8 partial diags) in smem
//   - reduces its 1024 S-elements (one float4/thread over 8 partials)
//   - hinge + block reduce -> g_loss_part[b]
//   - last block (atomic counter) sums 64 partials in fixed order -> out,
//     then resets the counter for the next graph replay.
// ---------------------------------------------------------------------------
__global__ void __launch_bounds__(256) fused_loss_kernel(float* __restrict__ out)
{
    __shared__ float diag_s[N_GROUPS];
    __shared__ float red[8];
    __shared__ int is_last;

    const int t = threadIdx.x;
    const int b = blockIdx.x;

    // diag[t] = sum_z Spart[z][t*257]
    {
        float d = 0.f;
        #pragma unroll
        for (int z = 0; z < KSPLIT; z++)
            d += g_Spart[(size_t)z * NPART + t * (N_GROUPS + 1)];
        diag_s[t] = d;
    }
    __syncthreads();

    // this thread's float4 of S
    const int q = b * 256 + t;          // 0..16383
    float4 v = make_float4(0.f, 0.f, 0.f, 0.f);
    #pragma unroll
    for (int z = 0; z < KSPLIT; z++) {
        float4 p = *(const float4*)&g_Spart[(size_t)z * NPART + q * 4];
        v.x += p.x; v.y += p.y; v.z += p.z; v.w += p.w;
    }

    const int i = q >> 6;
    const int j0 = (q & 63) * 4;
    const float di = diag_s[i];
    float vv[4] = {v.x, v.y, v.z, v.w};
    float sum = 0.f;
    #pragma unroll
    for (int c = 0; c < 4; c++) {
        int j = j0 + c;
        if (j != i)
            sum += fmaxf(vv[c] - di, 0.f) + fmaxf(vv[c] - diag_s[j], 0.f);
    }

    #pragma unroll
    for (int o = 16; o; o >>= 1) sum += __shfl_xor_sync(0xFFFFFFFFu, sum, o);
    if ((t & 31) == 0) red[t >> 5] = sum;
    __syncthreads();

    if (t == 0) {
        float bs = red[0] + red[1] + red[2] + red[3]
                 + red[4] + red[5] + red[6] + red[7];
        g_loss_part[b] = bs;
        __threadfence();
        int old = atomicAdd(&g_count, 1);
        is_last = (old == 63) ? 1 : 0;
    }
    __syncthreads();

    if (is_last) {
        if (t < 64) {
            float v2 = __ldcg(&g_loss_part[t]);   // L2-coherent read of other blocks' partials
            #pragma unroll
            for (int o = 16; o; o >>= 1) v2 += __shfl_xor_sync(0xFFFFFFFFu, v2, o);
            if (t == 0)  red[0] = v2;    // warp 0 sum (partials 0..31)
            if (t == 32) red[1] = v2;    // warp 1 sum (partials 32..63)
        }
        __syncthreads();
        if (t == 0) {
            out[0] = red[0] + red[1];
            g_count = 0;                 // reset for next replay
        }
    }
}

extern "C" void kernel_launch(void* const* d_in, const int* in_sizes, int n_in,
                              void* d_out, int out_size)
{
    const float* im        = (const float*)d_in[0];
    const float* s         = (const float*)d_in[1];
    const int*   num_clips = (const int*)d_in[2];
    const int*   num_caps  = (const int*)d_in[3];
    float* out = (float*)d_out;

    segmean_kernel<<<1024, 128>>>(im, s, num_clips, num_caps);
    gemm_partial_kernel<<<dim3(4, 4, KSPLIT), 256>>>();
    fused_loss_kernel<<<64, 256>>>(out);
}